// round 15
// baseline (speedup 1.0000x reference)
#include <cuda_runtime.h>
#include <cuda_bf16.h>
#include <math.h>
#include <stdint.h>

// ---------------------------------------------------------------------------
// ResidualAttentionBlock L=512 D=512 DC=256 T=128 FF=2048, P_COEF=0.5
// R15 (= R13 resubmit; broker timeouts, never ran):
// flash_mma unchanged (R12 WIN: 1336->679us, flash 236us).
// All dense GEMMs: FFMA -> mma.sync HMMA with split-bf16
// (hi*hi + hi*lo + lo*hi), fp32 accum. Fused bias/silu/resid epilogue.
// ---------------------------------------------------------------------------

#define O_X1   0
#define O_XT   (O_X1  + 512*512)
#define O_Q    (O_XT  + 1536*256)
#define O_KC   (O_Q   + 512*256)
#define O_ATT  (O_KC  + 512*256)
#define O_X2   (O_ATT + 512*256)
#define O_LN2  (O_X2  + 512*512)
#define O_H    (O_LN2 + 512*512)
#define O_PL   (O_H   + 512*2048)
#define O_PACC (O_PL  + 130*512)
#define BUF_TOTAL (O_PACC + 130*512*256)

__device__ float g_buf[BUF_TOTAL];

// ---------------- helpers ----------------
__device__ __forceinline__ uint32_t smem_u32(const void* p) {
    uint32_t a;
    asm("{ .reg .u64 t; cvta.to.shared.u64 t, %1; cvt.u32.u64 %0, t; }" : "=r"(a) : "l"(p));
    return a;
}

#define LDSM_X4(r0,r1,r2,r3, addr) \
    asm volatile("ldmatrix.sync.aligned.m8n8.x4.shared.b16 {%0,%1,%2,%3}, [%4];" \
                 : "=r"(r0), "=r"(r1), "=r"(r2), "=r"(r3) : "r"(addr))
#define LDSM_X2(r0,r1, addr) \
    asm volatile("ldmatrix.sync.aligned.m8n8.x2.shared.b16 {%0,%1}, [%2];" \
                 : "=r"(r0), "=r"(r1) : "r"(addr))
#define LDSM_X4T(r0,r1,r2,r3, addr) \
    asm volatile("ldmatrix.sync.aligned.m8n8.x4.trans.shared.b16 {%0,%1,%2,%3}, [%4];" \
                 : "=r"(r0), "=r"(r1), "=r"(r2), "=r"(r3) : "r"(addr))
#define MMA16816(c, a0,a1,a2,a3, b0,b1) \
    asm volatile("mma.sync.aligned.m16n8k16.row.col.f32.bf16.bf16.f32 " \
                 "{%0,%1,%2,%3}, {%4,%5,%6,%7}, {%8,%9}, {%0,%1,%2,%3};" \
                 : "+f"((c)[0]), "+f"((c)[1]), "+f"((c)[2]), "+f"((c)[3]) \
                 : "r"(a0), "r"(a1), "r"(a2), "r"(a3), "r"(b0), "r"(b1))

#define SCALE_Q (0.0625f*1.44269504088896f)

// flash dynamic smem layout (bytes): Q 64x256 | Khi 128x256 | Klo 128x256 | P 64x128
#define SQ_OFF  0
#define SKH_OFF 32768
#define SKL_OFF 98304
#define SP_OFF  163840
#define FL_BYTES 180224

// ---------------------------------------------------------------------------
// flash_mma (UNCHANGED from R12 passing version)
// ---------------------------------------------------------------------------
__global__ void __launch_bounds__(256, 1) flash_mma(
    const float* __restrict__ qg, const float* __restrict__ ck,
    const float* __restrict__ kc, const int* __restrict__ mask,
    float* __restrict__ pl, float* __restrict__ pacc)
{
    extern __shared__ char dyn[];
    __shared__ float lacc[64];
    __shared__ float ls2[2][64];
    uint32_t sbase = smem_u32(dyn);
    int tid = threadIdx.x, lane = tid & 31, wid = tid >> 5;
    int kb = blockIdx.x;

    const float* kbase;
    if (kb < 128) {
        if (mask[kb] == 0) return;
        kbase = ck + (size_t)kb * 512 * 256;
    } else if (kb == 128) kbase = kc;
    else kbase = qg;

    int strip = wid & 3;
    int khalf = wid >> 2;
    int gid = lane >> 2, tig = lane & 3;
    int sub = lane >> 3, r8 = lane & 7;
    int q0 = strip * 16;

    for (int qt = 0; qt < 8; qt++) {
        __syncthreads();
        if (tid < 64) lacc[tid] = 0.f;

        #pragma unroll
        for (int i = 0; i < 8; i++) {
            int m = tid + i*256;
            int row = m >> 5, ch = m & 31;
            const float* src = qg + (size_t)(qt*64 + row)*256 + ch*8;
            float4 v0 = *(const float4*)src;
            float4 v1 = *(const float4*)(src + 4);
            __nv_bfloat162 c0 = __floats2bfloat162_rn(v0.x*SCALE_Q, v0.y*SCALE_Q);
            __nv_bfloat162 c1 = __floats2bfloat162_rn(v0.z*SCALE_Q, v0.w*SCALE_Q);
            __nv_bfloat162 c2 = __floats2bfloat162_rn(v1.x*SCALE_Q, v1.y*SCALE_Q);
            __nv_bfloat162 c3 = __floats2bfloat162_rn(v1.z*SCALE_Q, v1.w*SCALE_Q);
            uint4 pk = make_uint4(*(uint32_t*)&c0, *(uint32_t*)&c1,
                                  *(uint32_t*)&c2, *(uint32_t*)&c3);
            *(uint4*)(dyn + SQ_OFF + row*512 + ((ch ^ (row & 7)) << 4)) = pk;
        }

        float o[16][4];
        #pragma unroll
        for (int i = 0; i < 16; i++) { o[i][0]=0.f; o[i][1]=0.f; o[i][2]=0.f; o[i][3]=0.f; }

        for (int it = 0; it < 4; it++) {
            __syncthreads();
            #pragma unroll
            for (int i = 0; i < 16; i++) {
                int m = tid + i*256;
                int row = m >> 5, ch = m & 31;
                const float* src = kbase + (size_t)(it*128 + row)*256 + ch*8;
                float4 v0 = *(const float4*)src;
                float4 v1 = *(const float4*)(src + 4);
                __nv_bfloat16 h[8];
                h[0]=__float2bfloat16_rn(v0.x); h[1]=__float2bfloat16_rn(v0.y);
                h[2]=__float2bfloat16_rn(v0.z); h[3]=__float2bfloat16_rn(v0.w);
                h[4]=__float2bfloat16_rn(v1.x); h[5]=__float2bfloat16_rn(v1.y);
                h[6]=__float2bfloat16_rn(v1.z); h[7]=__float2bfloat16_rn(v1.w);
                __nv_bfloat162 l0 = __floats2bfloat162_rn(v0.x-__bfloat162float(h[0]), v0.y-__bfloat162float(h[1]));
                __nv_bfloat162 l1 = __floats2bfloat162_rn(v0.z-__bfloat162float(h[2]), v0.w-__bfloat162float(h[3]));
                __nv_bfloat162 l2 = __floats2bfloat162_rn(v1.x-__bfloat162float(h[4]), v1.y-__bfloat162float(h[5]));
                __nv_bfloat162 l3 = __floats2bfloat162_rn(v1.z-__bfloat162float(h[6]), v1.w-__bfloat162float(h[7]));
                uint32_t off = row*512 + ((ch ^ (row & 7)) << 4);
                __nv_bfloat162 h01 = __halves2bfloat162(h[0], h[1]);
                __nv_bfloat162 h23 = __halves2bfloat162(h[2], h[3]);
                __nv_bfloat162 h45 = __halves2bfloat162(h[4], h[5]);
                __nv_bfloat162 h67 = __halves2bfloat162(h[6], h[7]);
                *(uint4*)(dyn + SKH_OFF + off) = make_uint4(*(uint32_t*)&h01, *(uint32_t*)&h23,
                                                            *(uint32_t*)&h45, *(uint32_t*)&h67);
                *(uint4*)(dyn + SKL_OFF + off) = make_uint4(*(uint32_t*)&l0, *(uint32_t*)&l1,
                                                            *(uint32_t*)&l2, *(uint32_t*)&l3);
            }
            __syncthreads();

            float c[8][4];
            #pragma unroll
            for (int i = 0; i < 8; i++) { c[i][0]=0.f; c[i][1]=0.f; c[i][2]=0.f; c[i][3]=0.f; }
            for (int ks = 0; ks < 16; ks++) {
                int arow = q0 + r8 + (sub & 1)*8;
                int ach  = 2*ks + (sub >> 1);
                uint32_t aaddr = sbase + SQ_OFF + arow*512 + ((ach ^ (arow & 7)) << 4);
                uint32_t a0,a1,a2,a3;
                LDSM_X4(a0,a1,a2,a3, aaddr);
                #pragma unroll
                for (int nt = 0; nt < 8; nt++) {
                    int l16  = lane & 15;
                    int brow = khalf*64 + nt*8 + (l16 & 7);
                    int bch  = 2*ks + (l16 >> 3);
                    uint32_t baddr = sbase + SKH_OFF + brow*512 + ((bch ^ (brow & 7)) << 4);
                    uint32_t b0,b1;
                    LDSM_X2(b0,b1, baddr);
                    MMA16816(c[nt], a0,a1,a2,a3, b0,b1);
                }
            }

            float rs0 = 0.f, rs1 = 0.f;
            #pragma unroll
            for (int nt = 0; nt < 8; nt++) {
                float p0 = exp2f(c[nt][0]), p1 = exp2f(c[nt][1]);
                float p2 = exp2f(c[nt][2]), p3 = exp2f(c[nt][3]);
                __nv_bfloat162 q01 = __floats2bfloat162_rn(p0, p1);
                __nv_bfloat162 q23 = __floats2bfloat162_rn(p2, p3);
                rs0 += __bfloat162float(__low2bfloat16(q01)) + __bfloat162float(__high2bfloat16(q01));
                rs1 += __bfloat162float(__low2bfloat16(q23)) + __bfloat162float(__high2bfloat16(q23));
                int key  = khalf*64 + nt*8 + 2*tig;
                int row0 = q0 + gid, row1 = row0 + 8;
                *(uint32_t*)(dyn + SP_OFF + row0*256 + (((key >> 3) ^ (row0 & 7)) << 4) + (key & 7)*2)
                    = *(uint32_t*)&q01;
                *(uint32_t*)(dyn + SP_OFF + row1*256 + (((key >> 3) ^ (row1 & 7)) << 4) + (key & 7)*2)
                    = *(uint32_t*)&q23;
            }
            rs0 += __shfl_xor_sync(0xffffffffu, rs0, 1);
            rs0 += __shfl_xor_sync(0xffffffffu, rs0, 2);
            rs1 += __shfl_xor_sync(0xffffffffu, rs1, 1);
            rs1 += __shfl_xor_sync(0xffffffffu, rs1, 2);
            if (tig == 0) {
                ls2[khalf][q0 + gid]     = rs0;
                ls2[khalf][q0 + gid + 8] = rs1;
            }
            __syncthreads();
            if (tid < 64) lacc[tid] += ls2[0][tid] + ls2[1][tid];

            for (int ks = 0; ks < 8; ks++) {
                int arow = q0 + r8 + (sub & 1)*8;
                int ach  = 2*ks + (sub >> 1);
                uint32_t aaddr = sbase + SP_OFF + arow*256 + ((ach ^ (arow & 7)) << 4);
                uint32_t a0,a1,a2,a3;
                LDSM_X4(a0,a1,a2,a3, aaddr);
                #pragma unroll
                for (int hs = 0; hs < 2; hs++) {
                    uint32_t voff = hs ? SKL_OFF : SKH_OFF;
                    #pragma unroll
                    for (int np = 0; np < 8; np++) {
                        int vrow = 16*ks + r8 + (sub & 1)*8;
                        int vch  = khalf*16 + np*2 + (sub >> 1);
                        uint32_t baddr = sbase + voff + vrow*512 + ((vch ^ (vrow & 7)) << 4);
                        uint32_t b0,b1,b2,b3;
                        LDSM_X4T(b0,b1,b2,b3, baddr);
                        MMA16816(o[np*2],     a0,a1,a2,a3, b0,b1);
                        MMA16816(o[np*2 + 1], a0,a1,a2,a3, b2,b3);
                    }
                }
            }
        }

        __syncthreads();
        float* stg = (float*)dyn;
        #pragma unroll
        for (int nt = 0; nt < 16; nt++) {
            int d = khalf*128 + nt*8 + 2*tig;
            stg[(q0 + gid)*260 + d]       = o[nt][0];
            stg[(q0 + gid)*260 + d + 1]   = o[nt][1];
            stg[(q0 + gid + 8)*260 + d]   = o[nt][2];
            stg[(q0 + gid + 8)*260 + d+1] = o[nt][3];
        }
        __syncthreads();
        if (tid < 64) pl[kb*512 + qt*64 + tid] = lacc[tid];
        float* dst = pacc + ((size_t)kb*512 + qt*64)*256;
        #pragma unroll
        for (int e = 0; e < 16; e++) {
            int idx = tid*4 + e*1024;
            int row = idx >> 8, d = idx & 255;
            *(float4*)&dst[idx] = *(const float4*)&stg[row*260 + d];
        }
    }
}

// ---------------------------------------------------------------------------
// gemm_mma: C[M,N] = A[M,K] @ B[K,N] (+bias)(+silu)(+resid), split-bf16 HMMA.
// 64x64 CTA tile, 256 thr (8 warps = 4 m-strips x 2 n-halves), K-chunk 32.
// 3 passes: Ahi*Bhi + Ahi*Blo + Alo*Bhi (lo*lo dropped). fp32 accumulate.
// A smem pitch 80B (conflict-free LDSM); B smem [k][n] XOR-swizzled (as flash AV).
// ---------------------------------------------------------------------------
__global__ void __launch_bounds__(256) gemm_mma(
    const float* __restrict__ A, const float* __restrict__ B,
    const float* __restrict__ bias, const float* __restrict__ resid,
    float* __restrict__ C, int M, int N, int K, int act)
{
    __shared__ __align__(16) char sm[18432];
    // Ah [64][pitch 80], Al +5120, Bh [32][128] +10240, Bl +14336
    uint32_t sb = smem_u32(sm);
    int tid = threadIdx.x, lane = tid & 31, wid = tid >> 5;
    int m0 = blockIdx.y * 64, n0 = blockIdx.x * 64;
    int mw = (wid & 3) * 16;
    int nw = (wid >> 2) * 32;
    int gid = lane >> 2, tig = lane & 3, sub = lane >> 3, r8 = lane & 7;

    float c[4][4];
    #pragma unroll
    for (int i = 0; i < 4; i++) { c[i][0]=0.f; c[i][1]=0.f; c[i][2]=0.f; c[i][3]=0.f; }

    for (int k0 = 0; k0 < K; k0 += 32) {
        __syncthreads();
        // ---- load A 64x32 (hi/lo) ----
        {
            int row = tid >> 2, cc = (tid & 3) * 8;
            const float* src = A + (size_t)(m0 + row)*K + k0 + cc;
            float4 v0 = *(const float4*)src, v1 = *(const float4*)(src + 4);
            __nv_bfloat16 h0=__float2bfloat16_rn(v0.x), h1=__float2bfloat16_rn(v0.y);
            __nv_bfloat16 h2=__float2bfloat16_rn(v0.z), h3=__float2bfloat16_rn(v0.w);
            __nv_bfloat16 h4=__float2bfloat16_rn(v1.x), h5=__float2bfloat16_rn(v1.y);
            __nv_bfloat16 h6=__float2bfloat16_rn(v1.z), h7=__float2bfloat16_rn(v1.w);
            __nv_bfloat162 p0=__halves2bfloat162(h0,h1), p1=__halves2bfloat162(h2,h3);
            __nv_bfloat162 p2=__halves2bfloat162(h4,h5), p3=__halves2bfloat162(h6,h7);
            __nv_bfloat162 l0=__floats2bfloat162_rn(v0.x-__bfloat162float(h0), v0.y-__bfloat162float(h1));
            __nv_bfloat162 l1=__floats2bfloat162_rn(v0.z-__bfloat162float(h2), v0.w-__bfloat162float(h3));
            __nv_bfloat162 l2=__floats2bfloat162_rn(v1.x-__bfloat162float(h4), v1.y-__bfloat162float(h5));
            __nv_bfloat162 l3=__floats2bfloat162_rn(v1.z-__bfloat162float(h6), v1.w-__bfloat162float(h7));
            uint32_t off = (uint32_t)row*80 + (uint32_t)(cc >> 3)*16;
            *(uint4*)(sm + off)        = make_uint4(*(uint32_t*)&p0, *(uint32_t*)&p1,
                                                    *(uint32_t*)&p2, *(uint32_t*)&p3);
            *(uint4*)(sm + 5120 + off) = make_uint4(*(uint32_t*)&l0, *(uint32_t*)&l1,
                                                    *(uint32_t*)&l2, *(uint32_t*)&l3);
        }
        // ---- load B 32x64 (hi/lo) ----
        {
            int kr = tid >> 3, cc = (tid & 7) * 8;
            const float* src = B + (size_t)(k0 + kr)*N + n0 + cc;
            float4 v0 = *(const float4*)src, v1 = *(const float4*)(src + 4);
            __nv_bfloat16 h0=__float2bfloat16_rn(v0.x), h1=__float2bfloat16_rn(v0.y);
            __nv_bfloat16 h2=__float2bfloat16_rn(v0.z), h3=__float2bfloat16_rn(v0.w);
            __nv_bfloat16 h4=__float2bfloat16_rn(v1.x), h5=__float2bfloat16_rn(v1.y);
            __nv_bfloat16 h6=__float2bfloat16_rn(v1.z), h7=__float2bfloat16_rn(v1.w);
            __nv_bfloat162 p0=__halves2bfloat162(h0,h1), p1=__halves2bfloat162(h2,h3);
            __nv_bfloat162 p2=__halves2bfloat162(h4,h5), p3=__halves2bfloat162(h6,h7);
            __nv_bfloat162 l0=__floats2bfloat162_rn(v0.x-__bfloat162float(h0), v0.y-__bfloat162float(h1));
            __nv_bfloat162 l1=__floats2bfloat162_rn(v0.z-__bfloat162float(h2), v0.w-__bfloat162float(h3));
            __nv_bfloat162 l2=__floats2bfloat162_rn(v1.x-__bfloat162float(h4), v1.y-__bfloat162float(h5));
            __nv_bfloat162 l3=__floats2bfloat162_rn(v1.z-__bfloat162float(h6), v1.w-__bfloat162float(h7));
            uint32_t off = (uint32_t)kr*128 + (uint32_t)(((cc >> 3) ^ (kr & 7)) << 4);
            *(uint4*)(sm + 10240 + off) = make_uint4(*(uint32_t*)&p0, *(uint32_t*)&p1,
                                                     *(uint32_t*)&p2, *(uint32_t*)&p3);
            *(uint4*)(sm + 14336 + off) = make_uint4(*(uint32_t*)&l0, *(uint32_t*)&l1,
                                                     *(uint32_t*)&l2, *(uint32_t*)&l3);
        }
        __syncthreads();

        #pragma unroll
        for (int ks = 0; ks < 2; ks++) {
            int arow = mw + r8 + (sub & 1)*8;
            uint32_t aoff = (uint32_t)arow*80 + (uint32_t)(ks*2 + (sub >> 1))*16;
            uint32_t ah0,ah1,ah2,ah3, al0,al1,al2,al3;
            LDSM_X4(ah0,ah1,ah2,ah3, sb + aoff);
            LDSM_X4(al0,al1,al2,al3, sb + 5120 + aoff);
            #pragma unroll
            for (int np = 0; np < 2; np++) {
                int vrow = ks*16 + r8 + (sub & 1)*8;
                int vch  = (nw >> 3) + np*2 + (sub >> 1);
                uint32_t boff = (uint32_t)vrow*128 + (uint32_t)((vch ^ (vrow & 7)) << 4);
                uint32_t bh0,bh1,bh2,bh3, bl0,bl1,bl2,bl3;
                LDSM_X4T(bh0,bh1,bh2,bh3, sb + 10240 + boff);
                LDSM_X4T(bl0,bl1,bl2,bl3, sb + 14336 + boff);
                MMA16816(c[np*2],     ah0,ah1,ah2,ah3, bh0,bh1);
                MMA16816(c[np*2 + 1], ah0,ah1,ah2,ah3, bh2,bh3);
                MMA16816(c[np*2],     ah0,ah1,ah2,ah3, bl0,bl1);
                MMA16816(c[np*2 + 1], ah0,ah1,ah2,ah3, bl2,bl3);
                MMA16816(c[np*2],     al0,al1,al2,al3, bh0,bh1);
                MMA16816(c[np*2 + 1], al0,al1,al2,al3, bh2,bh3);
            }
        }
    }

    // ---- epilogue ----
    #pragma unroll
    for (int nt = 0; nt < 4; nt++) {
        int n  = n0 + nw + nt*8 + 2*tig;
        int ma = m0 + mw + gid;
        int mb = ma + 8;
        float v0 = c[nt][0], v1 = c[nt][1], v2 = c[nt][2], v3 = c[nt][3];
        if (bias) {
            float b0 = bias[n], b1 = bias[n + 1];
            v0 += b0; v1 += b1; v2 += b0; v3 += b1;
        }
        if (act == 1) {
            v0 = v0 / (1.f + __expf(-1.702f * v0));
            v1 = v1 / (1.f + __expf(-1.702f * v1));
            v2 = v2 / (1.f + __expf(-1.702f * v2));
            v3 = v3 / (1.f + __expf(-1.702f * v3));
        }
        if (resid) {
            v0 += resid[(size_t)ma*N + n];
            v1 += resid[(size_t)ma*N + n + 1];
            v2 += resid[(size_t)mb*N + n];
            v3 += resid[(size_t)mb*N + n + 1];
        }
        C[(size_t)ma*N + n]     = v0;
        C[(size_t)ma*N + n + 1] = v1;
        C[(size_t)mb*N + n]     = v2;
        C[(size_t)mb*N + n + 1] = v3;
    }
}

// ---------------------------------------------------------------------------
// combine (unchanged)
// ---------------------------------------------------------------------------
__global__ void combine2(const float* __restrict__ pl, const float* __restrict__ pacc,
                         const float* __restrict__ qg, const int* __restrict__ mask,
                         float* __restrict__ att) {
    int qi = blockIdx.x, d = threadIdx.x;
    int nz = 0;
    float l = 0.f, a = 0.f;
    for (int kb = 0; kb < 129; kb++) {
        if (kb == 128 || mask[kb] != 0) {
            l += pl[kb*512 + qi];
            a += pacc[((size_t)kb*512 + qi)*256 + d];
        } else nz++;
    }
    l += 512.f * (float)nz;
    float ls = pl[129*512 + qi];
    float as_ = pacc[((size_t)129*512 + qi)*256 + d];
    float qv = qg[qi*256 + d];
    att[qi*256 + d] = a/l + 0.5f*as_/ls + 1.5f*qv;
}

// ---------------------------------------------------------------------------
// LayerNorm (unchanged)
// ---------------------------------------------------------------------------
__global__ void ln_kernel(const float* __restrict__ in, const float* __restrict__ g,
                          const float* __restrict__ b, float* __restrict__ out,
                          float* __restrict__ xt) {
    __shared__ float row[512];
    __shared__ float sred[16];
    int l = blockIdx.x, t = threadIdx.x;
    float v0 = in[l*512 + t];
    float v1 = in[l*512 + 256 + t];
    float s = v0 + v1, sq = v0*v0 + v1*v1;
    #pragma unroll
    for (int o = 16; o; o >>= 1) {
        s  += __shfl_xor_sync(0xffffffffu, s,  o);
        sq += __shfl_xor_sync(0xffffffffu, sq, o);
    }
    if ((t & 31) == 0) { sred[t >> 5] = s; sred[8 + (t >> 5)] = sq; }
    __syncthreads();
    if (t == 0) {
        float a = 0.f, c = 0.f;
        #pragma unroll
        for (int i = 0; i < 8; i++) { a += sred[i]; c += sred[8+i]; }
        sred[0] = a; sred[8] = c;
    }
    __syncthreads();
    float mean = sred[0] * (1.f/512.f);
    float var  = sred[8] * (1.f/512.f) - mean*mean;
    float rstd = rsqrtf(var + 1e-5f);
    float y0 = (v0 - mean) * rstd * g[t]       + b[t];
    float y1 = (v1 - mean) * rstd * g[256 + t] + b[256 + t];
    out[l*512 + t]       = y0;
    out[l*512 + 256 + t] = y1;
    if (xt) {
        row[t] = y0; row[256 + t] = y1;
        __syncthreads();
        #pragma unroll
        for (int k = 0; k < 3; k++) {
            int idx = 2*t + k - 1;
            float val = (idx >= 0) ? row[idx] : 0.f;
            xt[(l*3 + k)*256 + t] = val;
        }
    }
}

// ---------------------------------------------------------------------------
extern "C" void kernel_launch(void* const* d_in, const int* in_sizes, int n_in,
                              void* d_out, int out_size) {
    const float* x        = (const float*)d_in[0];
    const float* cached_k = (const float*)d_in[1];
    const float* ln1_g    = (const float*)d_in[2];
    const float* ln1_b    = (const float*)d_in[3];
    const float* ln2_g    = (const float*)d_in[4];
    const float* ln2_b    = (const float*)d_in[5];
    const float* wck      = (const float*)d_in[6];
    const float* wccur    = (const float*)d_in[7];
    const float* ap_w     = (const float*)d_in[8];
    const float* ap_b     = (const float*)d_in[9];
    const float* fc_w     = (const float*)d_in[10];
    const float* fc_b     = (const float*)d_in[11];
    const float* proj_w   = (const float*)d_in[12];
    const float* proj_b   = (const float*)d_in[13];
    const int*   mask     = (const int*)d_in[14];
    float* out = (float*)d_out;

    float* base = nullptr;
    cudaGetSymbolAddress((void**)&base, g_buf);
    float* x1   = base + O_X1;
    float* xt   = base + O_XT;
    float* q    = base + O_Q;
    float* kc   = base + O_KC;
    float* att  = base + O_ATT;
    float* x2   = base + O_X2;
    float* ln2v = base + O_LN2;
    float* h    = base + O_H;
    float* pl   = base + O_PL;
    float* pacc = base + O_PACC;

    // 1) ln1 + im2col
    ln_kernel<<<512, 256>>>(x, ln1_g, ln1_b, x1, xt);

    // 2) conv-as-GEMM: q and k_cur (HMMA)
    gemm_mma<<<dim3(256/64, 512/64), 256>>>(wck,   xt, nullptr, nullptr, q,  512, 256, 1536, 0);
    gemm_mma<<<dim3(256/64, 512/64), 256>>>(wccur, xt, nullptr, nullptr, kc, 512, 256, 1536, 0);

    // 3) HMMA flash attention
    cudaFuncSetAttribute(flash_mma, cudaFuncAttributeMaxDynamicSharedMemorySize, FL_BYTES);
    flash_mma<<<130, 256, FL_BYTES>>>(q, cached_k, kc, mask, pl, pacc);

    // 4) combine
    combine2<<<512, 256>>>(pl, pacc, q, mask, att);

    // 5) ap projection + residual(x1) -> x2 (HMMA)
    gemm_mma<<<dim3(512/64, 512/64), 256>>>(att, ap_w, ap_b, x1, x2, 512, 512, 256, 0);

    // 6) ln2
    ln_kernel<<<512, 256>>>(x2, ln2_g, ln2_b, ln2v, nullptr);

    // 7) fc + silu(1.702) (HMMA)
    gemm_mma<<<dim3(2048/64, 512/64), 256>>>(ln2v, fc_w, fc_b, nullptr, h, 512, 2048, 512, 1);

    // 8) proj + residual(x2) -> out (HMMA)
    gemm_mma<<<dim3(512/64, 512/64), 256>>>(h, proj_w, proj_b, x2, out, 512, 512, 2048, 0);
}